// round 1
// baseline (speedup 1.0000x reference)
#include <cuda_runtime.h>
#include <math.h>

#define SP    512
#define DIN   1536
#define NH    32
#define HD    128
#define HDTOT 4096

// ---------------- scratch (device globals; no allocations) ----------------
__device__ float g_xnorm[SP * DIN];
__device__ float g_xgelu[SP * DIN];
__device__ float g_q[SP * HDTOT];
__device__ float g_k[SP * HDTOT];
__device__ float g_yq[SP * HD];
__device__ float g_yk[SP * HD];
// suffix tables: [j 0..32][q 0..511][h 0..31][2] = {SA (incl b_pos term), SB}
__device__ float g_TQ[33 * SP * NH * 2];
__device__ float g_TK[33 * SP * NH * 2];
__device__ int   g_f0[SP];

// ---------------- K1: pool + rmsnorm + gelu ----------------
__global__ void k_pool(const float* __restrict__ x, const float* __restrict__ w_rms,
                       float* __restrict__ xnorm, float* __restrict__ xgelu) {
    int sp = blockIdx.x;
    const float* xb = x + (size_t)sp * 16 * DIN;
    __shared__ float xp[DIN];
    __shared__ float red[256];
    int t = threadIdx.x;
    float ssq = 0.f;
    for (int c = t; c < DIN; c += 256) {
        float s = 0.f;
        #pragma unroll
        for (int r = 0; r < 16; r++) s += xb[r * DIN + c];
        s *= (1.f / 16.f);
        xp[c] = s;
        ssq += s * s;
    }
    red[t] = ssq;
    __syncthreads();
    for (int o = 128; o > 0; o >>= 1) {
        if (t < o) red[t] += red[t + o];
        __syncthreads();
    }
    float scale = rsqrtf(red[0] / (float)DIN + 1e-6f);
    for (int c = t; c < DIN; c += 256) {
        float v = xp[c] * scale * w_rms[c];
        xnorm[sp * DIN + c] = v;
        xgelu[sp * DIN + c] = v * normcdff(v);  // exact gelu: x * Phi(x)
    }
}

// ---------------- K2: fp32 SGEMM  C[M,N] = A[M,K] @ B[K,N] ----------------
// BM=64 BN=64 BK=16, 256 threads, 4x4 per thread. M%64==0, N%64==0, K%16==0.
__global__ void __launch_bounds__(256) k_sgemm(const float* __restrict__ A,
                                               const float* __restrict__ B,
                                               float* __restrict__ C,
                                               int M, int N, int K) {
    __shared__ float As[16][64];
    __shared__ float Bs[16][68];
    int t = threadIdx.x;
    int m0 = blockIdx.y * 64, n0 = blockIdx.x * 64;
    int arow = t >> 2, acol = (t & 3) * 4;
    int brow = t >> 4, bcol = (t & 15) * 4;
    int tm = (t >> 4) * 4, tn = (t & 15) * 4;
    float acc[4][4];
    #pragma unroll
    for (int i = 0; i < 4; i++)
        #pragma unroll
        for (int j = 0; j < 4; j++) acc[i][j] = 0.f;

    for (int k0 = 0; k0 < K; k0 += 16) {
        float4 av = *(const float4*)&A[(size_t)(m0 + arow) * K + k0 + acol];
        As[acol + 0][arow] = av.x;
        As[acol + 1][arow] = av.y;
        As[acol + 2][arow] = av.z;
        As[acol + 3][arow] = av.w;
        float4 bv = *(const float4*)&B[(size_t)(k0 + brow) * N + n0 + bcol];
        *(float4*)&Bs[brow][bcol] = bv;
        __syncthreads();
        #pragma unroll
        for (int k = 0; k < 16; k++) {
            float a[4], b[4];
            *(float4*)a = *(const float4*)&As[k][tm];
            *(float4*)b = *(const float4*)&Bs[k][tn];
            #pragma unroll
            for (int i = 0; i < 4; i++)
                #pragma unroll
                for (int j = 0; j < 4; j++) acc[i][j] = fmaf(a[i], b[j], acc[i][j]);
        }
        __syncthreads();
    }
    #pragma unroll
    for (int i = 0; i < 4; i++) {
        float4 v = make_float4(acc[i][0], acc[i][1], acc[i][2], acc[i][3]);
        *(float4*)&C[(size_t)(m0 + tm + i) * N + n0 + tn] = v;
    }
}

// ---------------- K3: f0 table (count of center_widths <= d) ----------------
__global__ void k_f0(int* __restrict__ f0) {
    int d = threadIdx.x;
    if (d < SP) {
        const float log_step = (float)(log(481.0) / 32.0);  // log(512-32+1)/32
        int cnt = 0;
        #pragma unroll
        for (int f = 0; f < 32; f++) {
            float cw = (float)f + expf((float)f * log_step);
            if (cw <= (float)d) cnt++;
        }
        f0[d] = cnt;
    }
}

// ---------------- K4: suffix tables ----------------
// For each (h, q): M[f] = sum_c (qk[q,h,c]+rbias[h,c]) * W_pos[f, h*128+c], f<64
//                  Cb   = sum_c (..) * b_pos[h*128+c]
// SA[j] = Cb + sum_{f=j..31} M[f];  SB[j] = sum_{f=j..31} M[32+f]
// stored at T[((j*512+q)*32+h)*2 + {0,1}]
__global__ void __launch_bounds__(256) k_suffix(const float* __restrict__ qk,
                                                const float* __restrict__ rbias,
                                                const float* __restrict__ W_pos,
                                                const float* __restrict__ b_pos,
                                                float* __restrict__ T) {
    extern __shared__ float sm[];
    float* ws = sm;              // 65 rows (64 W_pos + 1 b_pos) x 132
    float* qs = ws + 65 * 132;   // 32 x 132
    float* Ms = qs + 32 * 132;   // 32 x 65
    int h = blockIdx.y;
    int q0 = blockIdx.x * 32;
    int t = threadIdx.x;

    for (int i = t; i < 65 * 128; i += 256) {
        int f = i >> 7, c = i & 127;
        float v = (f < 64) ? W_pos[f * HDTOT + h * HD + c] : b_pos[h * HD + c];
        ws[f * 132 + c] = v;
    }
    for (int i = t; i < 32 * 128; i += 256) {
        int r = i >> 7, c = i & 127;
        qs[r * 132 + c] = qk[(size_t)(q0 + r) * HDTOT + h * HD + c] + rbias[h * HD + c];
    }
    __syncthreads();
    for (int i = t; i < 32 * 65; i += 256) {
        int r = i / 65, f = i % 65;
        const float4* qr = (const float4*)&qs[r * 132];
        const float4* wr = (const float4*)&ws[f * 132];
        float acc = 0.f;
        #pragma unroll
        for (int c4 = 0; c4 < 32; c4++) {
            float4 a = qr[c4], b = wr[c4];
            acc += a.x * b.x + a.y * b.y + a.z * b.z + a.w * b.w;
        }
        Ms[r * 65 + f] = acc;
    }
    __syncthreads();
    for (int i = t; i < 32 * 33; i += 256) {
        int r = i / 33, j = i % 33;
        float sa = Ms[r * 65 + 64];  // b_pos contribution
        float sb = 0.f;
        for (int f = j; f < 32; f++) {
            sa += Ms[r * 65 + f];
            sb += Ms[r * 65 + 32 + f];
        }
        int q = q0 + r;
        int base = ((j * SP + q) * NH + h) * 2;
        T[base] = sa;
        T[base + 1] = sb;
    }
}

// ---------------- K5: fused pair kernel ----------------
// Per block: 32x32 (q,k) tile.
// pass1: A[q,k,h] = dot_c(qbuf, kbuf) per head, 2x2 reg blocking.
// rel:   A += 0.5*(term_q + term_k) via suffix-table gathers (f0 trick).
// pass2: out[q,k,d] = sum_h A*Wp[h,d] + b_pair[d] + yq[q,d] + yk[k,d]
#define AS_STRIDE 36   // pad 32->36 so each pair row is 144B (16B aligned)
__global__ void __launch_bounds__(256) k_pair(const float* __restrict__ qb,
                                              const float* __restrict__ kb,
                                              const float* __restrict__ TQ,
                                              const float* __restrict__ TK,
                                              const int* __restrict__ f0tab,
                                              const float* __restrict__ Wp,
                                              const float* __restrict__ bp,
                                              const float* __restrict__ yq,
                                              const float* __restrict__ yk,
                                              float* __restrict__ out) {
    extern __shared__ float sm[];
    float* As = sm;                       // 32*32*AS_STRIDE
    float* qs = As + 32 * 32 * AS_STRIDE; // 32*132
    float* ks = qs + 32 * 132;            // 32*132
    int t = threadIdx.x;
    int q0 = blockIdx.y * 32, k0 = blockIdx.x * 32;
    int ty = t >> 4, tx = t & 15;

    for (int h = 0; h < NH; h++) {
        __syncthreads();
        for (int i = t; i < 1024; i += 256) {
            int r = i >> 5, c4 = i & 31;
            *(float4*)&qs[r * 132 + c4 * 4] =
                *(const float4*)&qb[(size_t)(q0 + r) * HDTOT + h * HD + c4 * 4];
            *(float4*)&ks[r * 132 + c4 * 4] =
                *(const float4*)&kb[(size_t)(k0 + r) * HDTOT + h * HD + c4 * 4];
        }
        __syncthreads();
        float a00 = 0.f, a01 = 0.f, a10 = 0.f, a11 = 0.f;
        const float4* q0p = (const float4*)&qs[ty * 132];
        const float4* q1p = (const float4*)&qs[(ty + 16) * 132];
        const float4* k0p = (const float4*)&ks[tx * 132];
        const float4* k1p = (const float4*)&ks[(tx + 16) * 132];
        #pragma unroll
        for (int c4 = 0; c4 < 32; c4++) {
            float4 rq0 = q0p[c4], rq1 = q1p[c4], rk0 = k0p[c4], rk1 = k1p[c4];
            a00 += rq0.x * rk0.x + rq0.y * rk0.y + rq0.z * rk0.z + rq0.w * rk0.w;
            a01 += rq0.x * rk1.x + rq0.y * rk1.y + rq0.z * rk1.z + rq0.w * rk1.w;
            a10 += rq1.x * rk0.x + rq1.y * rk0.y + rq1.z * rk0.z + rq1.w * rk0.w;
            a11 += rq1.x * rk1.x + rq1.y * rk1.y + rq1.z * rk1.z + rq1.w * rk1.w;
        }
        As[(ty * 32 + tx) * AS_STRIDE + h] = a00;
        As[(ty * 32 + tx + 16) * AS_STRIDE + h] = a01;
        As[((ty + 16) * 32 + tx) * AS_STRIDE + h] = a10;
        As[((ty + 16) * 32 + tx + 16) * AS_STRIDE + h] = a11;
    }

    // relative-position terms (suffix-table gathers), each thread its own pairs
    #pragma unroll
    for (int p = 0; p < 4; p++) {
        int qi = (p >> 1) ? (ty + 16) : ty;
        int ki = (p & 1) ? (tx + 16) : tx;
        int q = q0 + qi, k = k0 + ki;
        int delta = k - q;
        int dd = delta >= 0 ? delta : -delta;
        float sgn = delta > 0 ? 1.f : (delta < 0 ? -1.f : 0.f);
        int j = f0tab[dd];
        const float4* tq4 = (const float4*)&TQ[(size_t)((j * SP + q) * NH) * 2];
        const float4* tk4 = (const float4*)&TK[(size_t)((j * SP + k) * NH) * 2];
        float* arow = &As[(qi * 32 + ki) * AS_STRIDE];
        #pragma unroll
        for (int h2 = 0; h2 < 16; h2++) {
            float4 a = tq4[h2], b = tk4[h2];
            arow[2 * h2]     += 0.5f * ((a.x + sgn * a.y) + (b.x - sgn * b.y));
            arow[2 * h2 + 1] += 0.5f * ((a.z + sgn * a.w) + (b.z - sgn * b.w));
        }
    }
    __syncthreads();

    // pass2: epilogue GEMM, W_pair column resident in registers
    int d = t & 127;
    int g = t >> 7;  // 0/1 -> two pairs per iteration
    float wcol[32];
    #pragma unroll
    for (int h = 0; h < 32; h++) wcol[h] = Wp[h * HD + d];
    float bpd = bp[d];
    for (int pp = 0; pp < 512; pp++) {
        int pair = pp * 2 + g;
        int qi = pair >> 5, ki = pair & 31;
        const float* arow = &As[pair * AS_STRIDE];
        float acc = bpd + yq[(q0 + qi) * HD + d] + yk[(k0 + ki) * HD + d];
        #pragma unroll
        for (int h4 = 0; h4 < 8; h4++) {
            float4 av = *(const float4*)&arow[h4 * 4];
            acc += av.x * wcol[h4 * 4] + av.y * wcol[h4 * 4 + 1] +
                   av.z * wcol[h4 * 4 + 2] + av.w * wcol[h4 * 4 + 3];
        }
        out[(size_t)((q0 + qi) * SP + (k0 + ki)) * HD + d] = acc;
    }
}

// ---------------- launcher ----------------
#define SUF_SMEM  ((65 * 132 + 32 * 132 + 32 * 65) * 4)
#define PAIR_SMEM ((32 * 32 * AS_STRIDE + 2 * 32 * 132) * 4)

extern "C" void kernel_launch(void* const* d_in, const int* in_sizes, int n_in,
                              void* d_out, int out_size) {
    const float* x      = (const float*)d_in[0];
    const float* w_rms  = (const float*)d_in[1];
    const float* W_q    = (const float*)d_in[2];
    const float* W_k    = (const float*)d_in[3];
    const float* W_pos  = (const float*)d_in[4];
    const float* b_pos  = (const float*)d_in[5];
    const float* qrb    = (const float*)d_in[6];
    const float* krb    = (const float*)d_in[7];
    const float* W_yq   = (const float*)d_in[8];
    const float* W_yk   = (const float*)d_in[9];
    const float* W_pair = (const float*)d_in[10];
    const float* b_pair = (const float*)d_in[11];
    float* out = (float*)d_out;

    float *xn, *xg, *qb, *kb, *yq, *yk, *TQ, *TK;
    int* f0;
    cudaGetSymbolAddress((void**)&xn, g_xnorm);
    cudaGetSymbolAddress((void**)&xg, g_xgelu);
    cudaGetSymbolAddress((void**)&qb, g_q);
    cudaGetSymbolAddress((void**)&kb, g_k);
    cudaGetSymbolAddress((void**)&yq, g_yq);
    cudaGetSymbolAddress((void**)&yk, g_yk);
    cudaGetSymbolAddress((void**)&TQ, g_TQ);
    cudaGetSymbolAddress((void**)&TK, g_TK);
    cudaGetSymbolAddress((void**)&f0, g_f0);

    cudaFuncSetAttribute(k_suffix, cudaFuncAttributeMaxDynamicSharedMemorySize, SUF_SMEM);
    cudaFuncSetAttribute(k_pair, cudaFuncAttributeMaxDynamicSharedMemorySize, PAIR_SMEM);

    k_pool<<<SP, 256>>>(x, w_rms, xn, xg);
    k_f0<<<1, 512>>>(f0);

    dim3 gqk(HDTOT / 64, SP / 64);
    k_sgemm<<<gqk, 256>>>(xn, W_q, qb, SP, HDTOT, DIN);
    k_sgemm<<<gqk, 256>>>(xn, W_k, kb, SP, HDTOT, DIN);
    dim3 gy(HD / 64, SP / 64);
    k_sgemm<<<gy, 256>>>(xg, W_yq, yq, SP, HD, DIN);
    k_sgemm<<<gy, 256>>>(xg, W_yk, yk, SP, HD, DIN);

    dim3 gs(SP / 32, NH);
    k_suffix<<<gs, 256, SUF_SMEM>>>(qb, qrb, W_pos, b_pos, TQ);
    k_suffix<<<gs, 256, SUF_SMEM>>>(kb, krb, W_pos, b_pos, TK);

    dim3 gp(SP / 32, SP / 32);
    k_pair<<<gp, 256, PAIR_SMEM>>>(qb, kb, TQ, TK, f0, W_pair, b_pair, yq, yk, out);
}